// round 1
// baseline (speedup 1.0000x reference)
#include <cuda_runtime.h>

// Hausdorff distance (squared), symmetric, per batch.
// preds: [B, N, 3] f32, gts: [B, N, 3] f32, out: [B] f32
// loss1 = max_j min_i ||p_i - g_j||^2 ; loss2 = max_i min_j ||p_i - g_j||^2
// out = 0.5*(loss1 + loss2)
//
// Strategy: d^2(p,g) = |p|^2 + (|g|^2 - 2 p.g). Inner points stored in shared
// as float4 (-2gx,-2gy,-2gz,|g|^2) -> 3 FFMA + 1 FMNMX per pair eval.
// |p|^2 added after the min (min is shift-invariant in it).

#define BATCH   16
#define NPTS    4096
#define THREADS 256
#define OPT     4                               // outer points per thread
#define CHUNKS  (NPTS / (THREADS * OPT))        // 4

// partial[dir][batch][chunk]; each slot written exactly once per launch.
__device__ float g_partial[2 * BATCH * CHUNKS];

__global__ void __launch_bounds__(THREADS)
hausdorff_main(const float* __restrict__ preds, const float* __restrict__ gts) {
    extern __shared__ float4 sh[];              // NPTS float4 = 64 KB

    const int chunk = blockIdx.x;
    const int b     = blockIdx.y;
    const int dir   = blockIdx.z;               // 0: outer=preds,inner=gts ; 1: swapped

    const float* __restrict__ outer = (dir == 0 ? preds : gts) + (size_t)b * NPTS * 3;
    const float* __restrict__ inner = (dir == 0 ? gts : preds) + (size_t)b * NPTS * 3;

    // Stage inner points into shared in the fused (-2g, |g|^2) format.
    for (int j = threadIdx.x; j < NPTS; j += THREADS) {
        float x = inner[j * 3 + 0];
        float y = inner[j * 3 + 1];
        float z = inner[j * 3 + 2];
        sh[j] = make_float4(-2.0f * x, -2.0f * y, -2.0f * z,
                            fmaf(x, x, fmaf(y, y, z * z)));
    }
    __syncthreads();

    // Each thread owns OPT outer points (strided for coalescing).
    float px[OPT], py[OPT], pz[OPT], rq[OPT], mn[OPT];
#pragma unroll
    for (int o = 0; o < OPT; o++) {
        int i = chunk * (THREADS * OPT) + o * THREADS + threadIdx.x;
        px[o] = outer[i * 3 + 0];
        py[o] = outer[i * 3 + 1];
        pz[o] = outer[i * 3 + 2];
        rq[o] = fmaf(px[o], px[o], fmaf(py[o], py[o], pz[o] * pz[o]));
        mn[o] = 3.4e38f;
    }

    // Main loop: 4096 inner points. 1 LDS.128 broadcast + OPT*(3 FFMA + 1 FMNMX).
#pragma unroll 4
    for (int j = 0; j < NPTS; j++) {
        float4 g = sh[j];
#pragma unroll
        for (int o = 0; o < OPT; o++) {
            float t = fmaf(g.x, px[o], g.w);
            t = fmaf(g.y, py[o], t);
            t = fmaf(g.z, pz[o], t);
            mn[o] = fminf(mn[o], t);
        }
    }

    // max_i ( |p_i|^2 + min_j(...) ) over this thread's outer points
    float mx = -3.4e38f;
#pragma unroll
    for (int o = 0; o < OPT; o++) mx = fmaxf(mx, rq[o] + mn[o]);

    // Block max reduction: warp shuffle then cross-warp via small shared array.
#pragma unroll
    for (int off = 16; off; off >>= 1)
        mx = fmaxf(mx, __shfl_xor_sync(0xffffffffu, mx, off));

    __shared__ float warpmax[THREADS / 32];
    if ((threadIdx.x & 31) == 0) warpmax[threadIdx.x >> 5] = mx;
    __syncthreads();

    if (threadIdx.x == 0) {
        float m = warpmax[0];
#pragma unroll
        for (int w = 1; w < THREADS / 32; w++) m = fmaxf(m, warpmax[w]);
        g_partial[(dir * BATCH + b) * CHUNKS + chunk] = m;
    }
}

__global__ void hausdorff_combine(float* __restrict__ out) {
    int b = threadIdx.x;
    if (b < BATCH) {
        float l2 = -3.4e38f;  // dir 0: max over preds of min over gts
        float l1 = -3.4e38f;  // dir 1: max over gts of min over preds
#pragma unroll
        for (int c = 0; c < CHUNKS; c++) {
            l2 = fmaxf(l2, g_partial[(0 * BATCH + b) * CHUNKS + c]);
            l1 = fmaxf(l1, g_partial[(1 * BATCH + b) * CHUNKS + c]);
        }
        out[b] = 0.5f * (l1 + l2);
    }
}

extern "C" void kernel_launch(void* const* d_in, const int* in_sizes, int n_in,
                              void* d_out, int out_size) {
    const float* preds = (const float*)d_in[0];
    const float* gts   = (const float*)d_in[1];
    float* out = (float*)d_out;

    const int smem = NPTS * sizeof(float4);  // 64 KB
    cudaFuncSetAttribute(hausdorff_main,
                         cudaFuncAttributeMaxDynamicSharedMemorySize, smem);

    dim3 grid(CHUNKS, BATCH, 2);
    hausdorff_main<<<grid, THREADS, smem>>>(preds, gts);
    hausdorff_combine<<<1, BATCH>>>(out);
}

// round 2
// speedup vs baseline: 1.2639x; 1.2639x over previous
#include <cuda_runtime.h>
#include <cfloat>

// Symmetric squared-Hausdorff per batch.
// d^2(p,g) = |p|^2 + (|g|^2 - 2 p.g).  min over inner is shift-invariant in
// |p|^2, which is added after the min.
//
// Packed-fp32 scheme: two INNER points are packed component-wise
// ({-2g0x,-2g1x}, {-2g0y,-2g1y}, {-2g0z,-2g1z}, {g0w,g1w}) so each
// fma.rn.f32x2 (SASS FFMA2, double-rate fp32) evaluates both candidates.
// Outer-point coordinates are duplicated into packed regs ONCE before the
// loop. Min uses two scalar FMNMX on the packed result's register halves
// (unpack = register aliasing, free).

#define BATCH   16
#define NPTS    4096
#define THREADS 256
#define OPT     4                       // outer points per thread
#define OCH     (NPTS / (THREADS*OPT))  // 4 outer chunks
#define ICH     8                       // inner chunks
#define ICN     (NPTS / ICH)            // 512 inner pts per chunk
#define IPAIRS  (ICN / 2)               // 256 packed pairs (== THREADS)

// partial min-d^2 per (dir, batch, inner-chunk, outer point); each slot
// written exactly once per launch -> deterministic, no init needed.
__device__ float g_partial[2][BATCH][ICH][NPTS];

typedef unsigned long long u64t;

__device__ __forceinline__ u64t fma2(u64t a, u64t b, u64t c) {
    u64t d;
    asm("fma.rn.f32x2 %0, %1, %2, %3;" : "=l"(d) : "l"(a), "l"(b), "l"(c));
    return d;
}
__device__ __forceinline__ u64t pk(float lo, float hi) {
    u64t d;
    asm("mov.b64 %0, {%1, %2};" : "=l"(d) : "f"(lo), "f"(hi));
    return d;
}
__device__ __forceinline__ float2 upk(u64t v) {
    float2 r;
    asm("mov.b64 {%0, %1}, %2;" : "=f"(r.x), "=f"(r.y) : "l"(v));
    return r;
}

__global__ void __launch_bounds__(THREADS)
hausdorff_main(const float* __restrict__ preds, const float* __restrict__ gts) {
    __shared__ __align__(16) ulonglong2 shv[IPAIRS * 2];

    const int ich = blockIdx.x & (ICH - 1);
    const int och = blockIdx.x >> 3;
    const int b   = blockIdx.y;
    const int dir = blockIdx.z;     // 0: outer=preds,inner=gts ; 1: swapped

    const float* __restrict__ outer = (dir == 0 ? preds : gts) + (size_t)b * NPTS * 3;
    const float* __restrict__ inner = (dir == 0 ? gts : preds) + (size_t)b * NPTS * 3;

    // ---- stage one inner pair per thread (512 pts / chunk) ----
    {
        float* shf = (float*)shv;
        const int pj = threadIdx.x;                         // pair index
        const float* gp = inner + (size_t)(ich * ICN + 2 * pj) * 3;
        float x0 = gp[0], y0 = gp[1], z0 = gp[2];
        float x1 = gp[3], y1 = gp[4], z1 = gp[5];
        shf[pj * 8 + 0] = -2.0f * x0;  shf[pj * 8 + 1] = -2.0f * x1;
        shf[pj * 8 + 2] = -2.0f * y0;  shf[pj * 8 + 3] = -2.0f * y1;
        shf[pj * 8 + 4] = -2.0f * z0;  shf[pj * 8 + 5] = -2.0f * z1;
        shf[pj * 8 + 6] = fmaf(x0, x0, fmaf(y0, y0, z0 * z0));
        shf[pj * 8 + 7] = fmaf(x1, x1, fmaf(y1, y1, z1 * z1));
    }
    __syncthreads();

    // ---- per-thread outer points, duplicated into packed regs once ----
    u64t px2[OPT], py2[OPT], pz2[OPT];
    float rq[OPT], mn[OPT];
    int oidx[OPT];
#pragma unroll
    for (int o = 0; o < OPT; o++) {
        int i = och * (THREADS * OPT) + o * THREADS + threadIdx.x;
        oidx[o] = i;
        float x = outer[i * 3 + 0];
        float y = outer[i * 3 + 1];
        float z = outer[i * 3 + 2];
        px2[o] = pk(x, x);
        py2[o] = pk(y, y);
        pz2[o] = pk(z, z);
        rq[o]  = fmaf(x, x, fmaf(y, y, z * z));
        mn[o]  = FLT_MAX;
    }

    // ---- main loop: per pair-iter: 2x LDS.128 + OPT*(3 FFMA2 + 2 FMNMX) ----
#pragma unroll 4
    for (int jp = 0; jp < IPAIRS; jp++) {
        ulonglong2 ab = shv[jp * 2 + 0];   // {gx2, gy2}
        ulonglong2 cd = shv[jp * 2 + 1];   // {gz2, gw2}
#pragma unroll
        for (int o = 0; o < OPT; o++) {
            u64t t = fma2(ab.x, px2[o], cd.y);
            t = fma2(ab.y, py2[o], t);
            t = fma2(cd.x, pz2[o], t);
            float2 tv = upk(t);
            mn[o] = fminf(mn[o], fminf(tv.x, tv.y));
        }
    }

    // ---- store per-outer-point partial (true min d^2 over this chunk) ----
    float* dst = &g_partial[dir][b][ich][0];
#pragma unroll
    for (int o = 0; o < OPT; o++)
        dst[oidx[o]] = mn[o] + rq[o];
}

__global__ void __launch_bounds__(THREADS)
hausdorff_combine(float* __restrict__ out) {
    const int b   = blockIdx.x;
    const int tid = threadIdx.x;

    float m0 = -FLT_MAX, m1 = -FLT_MAX;
#pragma unroll
    for (int it = 0; it < NPTS / (THREADS * 4); it++) {     // 4 iters
        int o = tid * 4 + it * THREADS * 4;
        float4 v0 = *(const float4*)&g_partial[0][b][0][o];
        float4 v1 = *(const float4*)&g_partial[1][b][0][o];
#pragma unroll
        for (int c = 1; c < ICH; c++) {
            float4 a = *(const float4*)&g_partial[0][b][c][o];
            float4 d = *(const float4*)&g_partial[1][b][c][o];
            v0.x = fminf(v0.x, a.x); v0.y = fminf(v0.y, a.y);
            v0.z = fminf(v0.z, a.z); v0.w = fminf(v0.w, a.w);
            v1.x = fminf(v1.x, d.x); v1.y = fminf(v1.y, d.y);
            v1.z = fminf(v1.z, d.z); v1.w = fminf(v1.w, d.w);
        }
        m0 = fmaxf(m0, fmaxf(fmaxf(v0.x, v0.y), fmaxf(v0.z, v0.w)));
        m1 = fmaxf(m1, fmaxf(fmaxf(v1.x, v1.y), fmaxf(v1.z, v1.w)));
    }

    // block max reduction for both directions
#pragma unroll
    for (int off = 16; off; off >>= 1) {
        m0 = fmaxf(m0, __shfl_xor_sync(0xffffffffu, m0, off));
        m1 = fmaxf(m1, __shfl_xor_sync(0xffffffffu, m1, off));
    }
    __shared__ float w0[THREADS / 32], w1[THREADS / 32];
    if ((tid & 31) == 0) { w0[tid >> 5] = m0; w1[tid >> 5] = m1; }
    __syncthreads();
    if (tid == 0) {
        float a = w0[0], c = w1[0];
#pragma unroll
        for (int w = 1; w < THREADS / 32; w++) {
            a = fmaxf(a, w0[w]);
            c = fmaxf(c, w1[w]);
        }
        out[b] = 0.5f * (a + c);
    }
}

extern "C" void kernel_launch(void* const* d_in, const int* in_sizes, int n_in,
                              void* d_out, int out_size) {
    const float* preds = (const float*)d_in[0];
    const float* gts   = (const float*)d_in[1];
    float* out = (float*)d_out;

    dim3 grid(OCH * ICH, BATCH, 2);    // 32 x 16 x 2 = 1024 blocks
    hausdorff_main<<<grid, THREADS>>>(preds, gts);
    hausdorff_combine<<<BATCH, THREADS>>>(out);
}